// round 17
// baseline (speedup 1.0000x reference)
#include <cuda_runtime.h>

// Problem constants (B=4, 96^3 vol, 4^3 patches, E=768)
#define TOKENS   13824
#define MASKN    10368
#define UNMASKN  3456
#define EDIM     768
#define KDIM     64
#define TT       16         // tokens per tile
#define NTHREADS 192        // 192 threads x 4 consecutive dims = 768
#define NW       6          // warps per block
#define UTILES   (UNMASKN / TT)   // 216
#define MTILES   (MASKN / TT)     // 648
#define NTILES   (BATCH * UTILES + MTILES)   // 1512
#define NBLOCKS  444        // 148 SMs x 3 resident blocks, persistent
#define BATCH    4
#define PSROW    20         // padded ps row (floats)
#define LOG2_1E4 13.287712379549449f

// positional-encoding table: g_pe[pos][c] = (c even ? sin : cos)(pos * 10000^-((c>>1)/128))
__device__ float g_pe[24][256];

__device__ __forceinline__ unsigned long long pack2(float a) {
    unsigned long long r;
    asm("mov.b64 %0, {%1, %1};" : "=l"(r) : "f"(a));
    return r;
}
__device__ __forceinline__ unsigned long long pack2b(float lo, float hi) {
    unsigned long long r;
    asm("mov.b64 %0, {%1, %2};" : "=l"(r) : "f"(lo), "f"(hi));
    return r;
}
__device__ __forceinline__ void fma2(unsigned long long& acc,
                                     unsigned long long a, unsigned long long b) {
    asm("fma.rn.f32x2 %0, %1, %2, %0;" : "+l"(acc) : "l"(a), "l"(b));
}
__device__ __forceinline__ void unpack2(unsigned long long v, float& lo, float& hi) {
    asm("mov.b64 {%0, %1}, %2;" : "=f"(lo), "=f"(hi) : "l"(v));
}

// Blocks [0,24): fill pe table row = blockIdx.x. Blocks [24,..): write mask_idx tail.
__global__ __launch_bounds__(256)
void init_pe_kernel(const int* __restrict__ perm, float* __restrict__ tail_out, int n_tail) {
    const int bi = blockIdx.x, tid = threadIdx.x;
    if (bi < 24) {
        const float invf = exp2f(-(float)(tid >> 1) * (LOG2_1E4 / 128.0f));
        float s, c;
        sincosf((float)bi * invf, &s, &c);
        g_pe[bi][tid] = (tid & 1) ? c : s;
    } else {
        const int i = (bi - 24) * 256 + tid;
        if (i < n_tail) tail_out[i] = (float)perm[i];
    }
}

// PERSISTENT blocks: 444 blocks grid-stride over 1512 tiles of 16 tokens x 768 dims.
// Thread owns dims 4*tid..4*tid+3 (one pe segment). Per-thread constants hoisted
// outside the tile loop. TWO-PASS epilogue streams over acc (no v[] duplicate).
// Tiles [0, 864): unmask per batch. Tiles [864, 1512): mask tokens,
// computed once, written to all 4 batches (batch-invariant incl. LN).
__global__ __launch_bounds__(NTHREADS, 3)
void embed_kernel(const float* __restrict__ x,
                  const float* __restrict__ W,
                  const float* __restrict__ bias,
                  const float* __restrict__ mtok,
                  const float* __restrict__ gamma,
                  const float* __restrict__ beta,
                  const int*   __restrict__ perm,
                  float* __restrict__ out)
{
    __shared__ float ps[KDIM][PSROW];       // patch tile, k-major; token pairs contiguous
    __shared__ int   sH[TT], sW[TT], sD[TT];
    __shared__ float redS[TT][NW + 1], redQ[TT][NW + 1];
    __shared__ float meanv[TT], rstdv[TT];

    const int tid = threadIdx.x;
    const int warp = tid >> 5, lane = tid & 31;

    // ---- hoisted per-thread constants (dims fixed for whole kernel) ----
    const float4 b4  = *((const float4*)bias + tid);
    const float4 g4  = *((const float4*)gamma + tid);
    const float4 be4 = *((const float4*)beta + tid);
    const unsigned long long B0c = pack2(b4.x), B1c = pack2(b4.y),
                             B2c = pack2(b4.z), B3c = pack2(b4.w);
    const int pecol = (tid & 63) * 4;
    const float4* wp4 = (const float4*)W + tid;
    const size_t bstride4 = (size_t)TOKENS * (EDIM / 4);

    for (int ti = blockIdx.x; ti < NTILES; ti += NBLOCKS) {
        const bool is_mask = ti >= BATCH * UTILES;
        int b = 0, tile;
        if (!is_mask) { b = ti / UTILES; tile = ti % UTILES; }
        else          { tile = ti - BATCH * UTILES; }

        __syncthreads();   // previous iteration's smem readers done before restage

        // ---- stage: gather 16 patch rows (64 floats each) into SMEM ----
        for (int it = tid; it < TT * 16; it += NTHREADS) {
            const int tok = it & 15;
            const int seg = it >> 4;
            const int m   = tile * TT + tok;
            const int s   = is_mask ? perm[m] : perm[MASKN + m];
            const int h = s / 576, w = (s % 576) / 24, d = s % 24;
            if (seg == 0) { sH[tok] = h; sW[tok] = w; sD[tok] = d; }
            float4 v;
            if (!is_mask) {
                const int i = seg >> 2, j = seg & 3;
                const size_t xi = (((size_t)(b * 96 + 4 * h + i)) * 96 + (4 * w + j)) * 96 + 4 * d;
                v = *(const float4*)(x + xi);
            } else {
                v = *(const float4*)(mtok + (size_t)m * KDIM + seg * 4);
            }
            const int p = seg * 4;
            ps[p + 0][tok] = v.x; ps[p + 1][tok] = v.y;
            ps[p + 2][tok] = v.z; ps[p + 3][tok] = v.w;
        }
        __syncthreads();

        // ---- GEMM: thread owns 4 consecutive dims; acc = token pairs (f32x2) ----
        unsigned long long a0[8], a1[8], a2[8], a3[8];
        #pragma unroll
        for (int t = 0; t < 8; t++) { a0[t] = B0c; a1[t] = B1c; a2[t] = B2c; a3[t] = B3c; }

        #pragma unroll 2
        for (int k = 0; k < KDIM; k++) {
            const float4 w4 = wp4[k * (EDIM / 4)];
            const unsigned long long W0 = pack2(w4.x), W1 = pack2(w4.y),
                                     W2 = pack2(w4.z), W3 = pack2(w4.w);
            const ulonglong2* pp2 = (const ulonglong2*)ps[k];   // broadcast LDS.128
            #pragma unroll
            for (int q = 0; q < 4; q++) {
                const ulonglong2 pd = pp2[q];
                fma2(a0[2 * q],     pd.x, W0);
                fma2(a1[2 * q],     pd.x, W1);
                fma2(a2[2 * q],     pd.x, W2);
                fma2(a3[2 * q],     pd.x, W3);
                fma2(a0[2 * q + 1], pd.y, W0);
                fma2(a1[2 * q + 1], pd.y, W1);
                fma2(a2[2 * q + 1], pd.y, W2);
                fma2(a3[2 * q + 1], pd.y, W3);
            }
        }

        // thread's 4 dims live in one pe segment: tid<64 -> H, <128 -> W, else D
        const int* sposArr = (tid < 64) ? sH : (tid < 128) ? sW : sD;

        // ---- epilogue PASS 1: stream over acc: +pe (repacked in place), LN stats ----
        #pragma unroll
        for (int t2 = 0; t2 < 8; t2++) {
            const int ta = 2 * t2, tb = ta + 1;
            float x0a, x0b, x1a, x1b, x2a, x2b, x3a, x3b;
            unpack2(a0[t2], x0a, x0b);
            unpack2(a1[t2], x1a, x1b);
            unpack2(a2[t2], x2a, x2b);
            unpack2(a3[t2], x3a, x3b);
            const float4 pa = __ldg((const float4*)&g_pe[sposArr[ta]][pecol]);
            const float4 pb = __ldg((const float4*)&g_pe[sposArr[tb]][pecol]);
            x0a += pa.x; x1a += pa.y; x2a += pa.z; x3a += pa.w;
            x0b += pb.x; x1b += pb.y; x2b += pb.z; x3b += pb.w;
            a0[t2] = pack2b(x0a, x0b);
            a1[t2] = pack2b(x1a, x1b);
            a2[t2] = pack2b(x2a, x2b);
            a3[t2] = pack2b(x3a, x3b);

            float sma = x0a + x1a + x2a + x3a;
            float sqa = x0a * x0a + x1a * x1a + x2a * x2a + x3a * x3a;
            float smb = x0b + x1b + x2b + x3b;
            float sqb = x0b * x0b + x1b * x1b + x2b * x2b + x3b * x3b;
            #pragma unroll
            for (int off = 16; off > 0; off >>= 1) {
                sma += __shfl_xor_sync(0xffffffffu, sma, off);
                sqa += __shfl_xor_sync(0xffffffffu, sqa, off);
                smb += __shfl_xor_sync(0xffffffffu, smb, off);
                sqb += __shfl_xor_sync(0xffffffffu, sqb, off);
            }
            if (lane == 0) {
                redS[ta][warp] = sma; redQ[ta][warp] = sqa;
                redS[tb][warp] = smb; redQ[tb][warp] = sqb;
            }
        }
        __syncthreads();

        if (tid < TT) {
            float sm = 0.f, sq = 0.f;
            #pragma unroll
            for (int wi = 0; wi < NW; wi++) { sm += redS[tid][wi]; sq += redQ[tid][wi]; }
            const float mn = sm * (1.0f / (float)EDIM);
            const float vr = sq * (1.0f / (float)EDIM) - mn * mn;
            meanv[tid] = mn;
            rstdv[tid] = rsqrtf(vr + 0.001f);
        }
        __syncthreads();

        // ---- epilogue PASS 2: normalize + store (pe already folded into acc) ----
        if (!is_mask) {
            float4* o = (float4*)(out + ((size_t)b * TOKENS + (size_t)tile * TT) * EDIM) + tid;
            #pragma unroll
            for (int t2 = 0; t2 < 8; t2++) {
                const int ta = 2 * t2, tb = ta + 1;
                float x0a, x0b, x1a, x1b, x2a, x2b, x3a, x3b;
                unpack2(a0[t2], x0a, x0b);
                unpack2(a1[t2], x1a, x1b);
                unpack2(a2[t2], x2a, x2b);
                unpack2(a3[t2], x3a, x3b);
                const float mna = meanv[ta], rsa = rstdv[ta];
                const float mnb = meanv[tb], rsb = rstdv[tb];
                float4 ra, rb;
                ra.x = (x0a - mna) * rsa * g4.x + be4.x;
                ra.y = (x1a - mna) * rsa * g4.y + be4.y;
                ra.z = (x2a - mna) * rsa * g4.z + be4.z;
                ra.w = (x3a - mna) * rsa * g4.w + be4.w;
                rb.x = (x0b - mnb) * rsb * g4.x + be4.x;
                rb.y = (x1b - mnb) * rsb * g4.y + be4.y;
                rb.z = (x2b - mnb) * rsb * g4.z + be4.z;
                rb.w = (x3b - mnb) * rsb * g4.w + be4.w;
                o[(size_t)ta * (EDIM / 4)] = ra;
                o[(size_t)tb * (EDIM / 4)] = rb;
            }
        } else {
            float4* o = (float4*)(out + ((size_t)UNMASKN + (size_t)tile * TT) * EDIM) + tid;
            #pragma unroll
            for (int t2 = 0; t2 < 8; t2++) {
                const int ta = 2 * t2, tb = ta + 1;
                float x0a, x0b, x1a, x1b, x2a, x2b, x3a, x3b;
                unpack2(a0[t2], x0a, x0b);
                unpack2(a1[t2], x1a, x1b);
                unpack2(a2[t2], x2a, x2b);
                unpack2(a3[t2], x3a, x3b);
                const float mna = meanv[ta], rsa = rstdv[ta];
                const float mnb = meanv[tb], rsb = rstdv[tb];
                float4 ra, rb;
                ra.x = (x0a - mna) * rsa * g4.x + be4.x;
                ra.y = (x1a - mna) * rsa * g4.y + be4.y;
                ra.z = (x2a - mna) * rsa * g4.z + be4.z;
                ra.w = (x3a - mna) * rsa * g4.w + be4.w;
                rb.x = (x0b - mnb) * rsb * g4.x + be4.x;
                rb.y = (x1b - mnb) * rsb * g4.y + be4.y;
                rb.z = (x2b - mnb) * rsb * g4.z + be4.z;
                rb.w = (x3b - mnb) * rsb * g4.w + be4.w;
                float4* oa = o + (size_t)ta * (EDIM / 4);
                float4* ob = o + (size_t)tb * (EDIM / 4);
                #pragma unroll
                for (int bb = 0; bb < BATCH; bb++) {
                    oa[bb * bstride4] = ra;
                    ob[bb * bstride4] = rb;
                }
            }
        }
    }
}

extern "C" void kernel_launch(void* const* d_in, const int* in_sizes, int n_in,
                              void* d_out, int out_size) {
    const float* x     = (const float*)d_in[0];
    const float* W     = (const float*)d_in[1];
    const float* bias  = (const float*)d_in[2];
    const float* mtok  = (const float*)d_in[3];
    const float* gamma = (const float*)d_in[4];
    const float* beta  = (const float*)d_in[5];
    const int*   perm  = (const int*)d_in[6];
    float* out = (float*)d_out;

    const long long main_elems = (long long)BATCH * TOKENS * EDIM;  // 42,467,328
    const long long extra = (long long)out_size - main_elems;       // expected 10368 (mask_idx)
    const int n_tail = extra > 0 ? (int)extra : 0;
    const int tail_blocks = (n_tail + 255) / 256;

    // init: pe table (24 blocks) + mask_idx tail writes
    init_pe_kernel<<<24 + tail_blocks, 256>>>(perm, out + main_elems, n_tail);

    embed_kernel<<<NBLOCKS, NTHREADS>>>(x, W, bias, mtok, gamma, beta, perm, out);
}